// round 9
// baseline (speedup 1.0000x reference)
#include <cuda_runtime.h>
#include <math.h>

#define B_SZ 32
#define T_SZ 1024
#define I_SZ 512
#define H_SZ 1024
#define DT_C 0.1f

typedef unsigned long long ull;

// ---------------- f32x2 packed-math helpers (Blackwell FFMA2) -------------
__device__ __forceinline__ ull ffma2(ull a, ull b, ull c) {
    ull d; asm("fma.rn.f32x2 %0, %1, %2, %3;" : "=l"(d) : "l"(a), "l"(b), "l"(c)); return d;
}
__device__ __forceinline__ ull fadd2(ull a, ull b) {
    ull d; asm("add.rn.f32x2 %0, %1, %2;" : "=l"(d) : "l"(a), "l"(b)); return d;
}
__device__ __forceinline__ ull pack2(float lo, float hi) {
    ull d; asm("mov.b64 %0, {%1, %2};" : "=l"(d) : "f"(lo), "f"(hi)); return d;
}
__device__ __forceinline__ float2 unpack2(ull v) {
    float2 r; asm("mov.b64 {%0, %1}, %2;" : "=f"(r.x), "=f"(r.y) : "l"(v)); return r;
}

// ------------------------------------------------------------------
// Persistent-kernel global state
// g_hT: transposed hidden state double buffer: [2][H][B]  (k-major)
// Barrier flags: one per 128B line; two independent 64-block groups.
// ------------------------------------------------------------------
#define RBLK 128
#define FPAD 32                      // ints per flag slot (128B line)
__device__ float g_hT[2][H_SZ * B_SZ];
__device__ volatile int g_arrive[RBLK * FPAD];
__device__ volatile int g_release[2 * FPAD];

__global__ void reset_kernel() {
    int idx = blockIdx.x * blockDim.x + threadIdx.x;
    if (idx < H_SZ * B_SZ) g_hT[0][idx] = 0.0f;
    if (idx < RBLK * FPAD) g_arrive[idx] = 0;
    if (idx < 2 * FPAD) g_release[idx] = 0;
}

// ------------------------------------------------------------------
// xW GEMM: C[M=B*T, H] = X[M, I] @ W[H, I]^T   (fp32, FFMA2 inner)
// 128x64 block tile, BK=16, 256 threads
// ------------------------------------------------------------------
#define GBM 128
#define GBN 64
#define GBK 16

union F4U { float4 f4; ull u[2]; };

__global__ void __launch_bounds__(256) gemm_xw(
    const float* __restrict__ X, const float* __restrict__ W,
    float* __restrict__ C)
{
    __shared__ float Xs[GBK][GBM];
    __shared__ float Ws[GBK][GBN + 4];
    const int tid = threadIdx.x;
    const int tx = tid & 15;   // 16 -> N
    const int ty = tid >> 4;   // 16 -> M
    const int m0 = blockIdx.y * GBM;
    const int n0 = blockIdx.x * GBN;

    ull acc2[4][4];   // [m-pair p][n j]
#pragma unroll
    for (int p = 0; p < 4; p++)
#pragma unroll
        for (int j = 0; j < 4; j++) acc2[p][j] = 0ull;

    for (int k0 = 0; k0 < I_SZ; k0 += GBK) {
#pragma unroll
        for (int pp = 0; pp < 2; pp++) {
            int q = tid + pp * 256;
            int row = q >> 2, qc = q & 3;
            float4 v = *(const float4*)(X + (size_t)(m0 + row) * I_SZ + k0 + qc * 4);
            Xs[qc * 4 + 0][row] = v.x; Xs[qc * 4 + 1][row] = v.y;
            Xs[qc * 4 + 2][row] = v.z; Xs[qc * 4 + 3][row] = v.w;
        }
        {
            int row = tid >> 2, qc = tid & 3;
            float4 v = *(const float4*)(W + (size_t)(n0 + row) * I_SZ + k0 + qc * 4);
            Ws[qc * 4 + 0][row] = v.x; Ws[qc * 4 + 1][row] = v.y;
            Ws[qc * 4 + 2][row] = v.z; Ws[qc * 4 + 3][row] = v.w;
        }
        __syncthreads();
#pragma unroll
        for (int kk = 0; kk < GBK; kk++) {
            F4U a0, a1;
            a0.f4 = *(const float4*)&Xs[kk][ty * 8];
            a1.f4 = *(const float4*)&Xs[kk][ty * 8 + 4];
            float4 bv = *(const float4*)&Ws[kk][tx * 4];
            ull bd[4];
            bd[0] = pack2(bv.x, bv.x); bd[1] = pack2(bv.y, bv.y);
            bd[2] = pack2(bv.z, bv.z); bd[3] = pack2(bv.w, bv.w);
            ull a2[4] = {a0.u[0], a0.u[1], a1.u[0], a1.u[1]};
#pragma unroll
            for (int p = 0; p < 4; p++)
#pragma unroll
                for (int j = 0; j < 4; j++)
                    acc2[p][j] = ffma2(a2[p], bd[j], acc2[p][j]);
        }
        __syncthreads();
    }
#pragma unroll
    for (int p = 0; p < 4; p++) {
        float2 c0 = unpack2(acc2[p][0]);
        float2 c1 = unpack2(acc2[p][1]);
        float2 c2 = unpack2(acc2[p][2]);
        float2 c3 = unpack2(acc2[p][3]);
        float4 lo = make_float4(c0.x, c1.x, c2.x, c3.x);
        float4 hi = make_float4(c0.y, c1.y, c2.y, c3.y);
        *(float4*)(C + (size_t)(m0 + ty * 8 + 2 * p)     * H_SZ + n0 + tx * 4) = lo;
        *(float4*)(C + (size_t)(m0 + ty * 8 + 2 * p + 1) * H_SZ + n0 + tx * 4) = hi;
    }
}

// ------------------------------------------------------------------
// Persistent recurrence kernel.
// grid = 128 blocks (64 j-tiles x 2 b-halves), 512 threads.
// Block tile per step: 16 j x 16 b x 1024 k.
// Thread (tb=tid&1, tj=(tid>>1)&3, ks=tid>>3): 4j x 4 b-pairs x 16k.
// U lives ENTIRELY in registers: u[4][16] (64 regs/thread).
// h staged k-major: hs[k][16 b], stride 20 (conflict-free LDS.64).
// Barrier: two independent 64-block two-hop groups (R8-proven).
// ------------------------------------------------------------------
#define JT 16
#define BHALF 16
#define HSTR 20
#define NPO 128
#define RECUR_SMEM ((H_SZ * HSTR + 2 * NPO) * 4 + NPO * 64 * 8)

__global__ void __launch_bounds__(512, 1) recur_kernel(
    float* __restrict__ states,      // [B, T, H] (holds xW on entry, states on exit)
    float* __restrict__ hfinal,      // [B, H]
    const float* __restrict__ U,     // [H, H]
    const float* __restrict__ bias,  // [H]
    const float* __restrict__ tau)   // [H]
{
    extern __shared__ float sm[];
    float* hs = sm;                                 // [1024][HSTR]
    ull* red = (ull*)(hs + H_SZ * HSTR);            // [NPO][64]
    float* epi = (float*)(red + NPO * 64);          // [2*NPO]: decay, bias

    const int tid = threadIdx.x;
    const int blk = blockIdx.x;
    const int jt = blk & 63;
    const int bh = blk >> 6;
    const int j0 = jt * JT;
    const int bg0 = bh * BHALF;
    const int gbase = bh << 6;        // first block of this barrier group
    const bool leader = (jt == 0);    // block 0 / block 64 lead their groups

    const int tb = tid & 1;
    const int tj = (tid >> 1) & 3;
    const int ks = tid >> 3;      // 0..63

    // ---- U slab entirely into registers: u[jj][kq] = U[j0+tj*4+jj][ks+64kq]
    float u[4][16];
    {
        const float* ub = U + (size_t)(j0 + tj * 4) * H_SZ + ks;
#pragma unroll
        for (int jj = 0; jj < 4; jj++)
#pragma unroll
            for (int kq = 0; kq < 16; kq++)
                u[jj][kq] = __ldg(ub + (size_t)jj * H_SZ + kq * 64);
    }

    // ---- epilogue (reader) setup: tid < 128, sr = tid & 15 ----
    int po = 0, sr = 0, jg = 0, bp = 0;
    size_t sidx0 = 0;
    float xwA = 0.0f, xwB = 0.0f;
    if (tid < NPO) {
        int r = tid;
        po = ((r >> 1) & 1) | ((r & 1) << 1) | (((r >> 4) & 1) << 2)
           | (((r >> 5) & 1) << 3) | (((r >> 6) & 1) << 4)
           | (((r >> 2) & 1) << 5) | (((r >> 3) & 1) << 6);
        sr = r & 15;
        int j_loc = po >> 3;
        bp = po & 7;
        jg = j0 + j_loc;
        float it = 1.0f / tau[jg];
        epi[tid] = 1.0f - DT_C * it;     // decay
        epi[NPO + tid] = bias[jg];       // bias
        int b_glob = bg0 + 2 * bp;
        sidx0 = (size_t)b_glob * T_SZ * H_SZ + jg;
        xwA = __ldcg(states + sidx0);                          // prefetch t = 0
        xwB = __ldcg(states + sidx0 + (size_t)T_SZ * H_SZ);
    }

    int cur = 0;
    __syncthreads();

    for (int t = 0; t < T_SZ; t++) {
        // ---- stage h^T half-slab: hs[k][0..15] <- g_hT[cur][k][bg0..+15] ----
        const float* gh = g_hT[cur] + bg0;
#pragma unroll
        for (int it8 = 0; it8 < 8; it8++) {
            int q = tid + it8 * 512;
            int k = q >> 2, part = (q & 3) * 4;
            float4 v = __ldcg((const float4*)(gh + (size_t)k * B_SZ + part));
            float* d = hs + k * HSTR + part;
            d[0] = v.x; d[1] = v.y; d[2] = v.z; d[3] = v.w;
        }
        __syncthreads();

        // ---- compute: acc2[jj][m] over k = ks + 64*kq, u from registers ----
        ull acc2[4][4];
#pragma unroll
        for (int jj = 0; jj < 4; jj++)
#pragma unroll
            for (int m = 0; m < 4; m++) acc2[jj][m] = 0ull;

#pragma unroll
        for (int kq = 0; kq < 16; kq++) {
            int k = ks + 64 * kq;
            const float* hrow = hs + k * HSTR + 2 * tb;
            ull h0 = *(const ull*)(hrow + 0);
            ull h1 = *(const ull*)(hrow + 4);
            ull h2 = *(const ull*)(hrow + 8);
            ull h3 = *(const ull*)(hrow + 12);
#pragma unroll
            for (int jj = 0; jj < 4; jj++) {
                ull ud = pack2(u[jj][kq], u[jj][kq]);
                acc2[jj][0] = ffma2(ud, h0, acc2[jj][0]);
                acc2[jj][1] = ffma2(ud, h1, acc2[jj][1]);
                acc2[jj][2] = ffma2(ud, h2, acc2[jj][2]);
                acc2[jj][3] = ffma2(ud, h3, acc2[jj][3]);
            }
        }

        // ---- write partials, XOR-swizzled (2-phase-optimal STS.64) ----
#pragma unroll
        for (int jj = 0; jj < 4; jj++)
#pragma unroll
            for (int m = 0; m < 4; m++) {
                int p = (tj * 4 + jj) * 8 + 2 * m + tb;
                int col = ks ^ ((m & 1) | (tb << 1) | (tj << 2));
                red[p * 64 + col] = acc2[jj][m];
            }
        __syncthreads();

        // ---- reduce + pointwise epilogue (128 readers) ----
        if (tid < NPO) {
            ull s01 = 0ull, s23 = 0ull;
#pragma unroll
            for (int i = 0; i < 64; i += 2) {
                s01 = fadd2(s01, red[po * 64 + (i ^ sr)]);
                s23 = fadd2(s23, red[po * 64 + ((i + 1) ^ sr)]);
            }
            float2 sum = unpack2(fadd2(s01, s23));
            float2 hold = *(const float2*)(hs + jg * HSTR + 2 * bp);
            float decay = epi[tid];
            float biasj = epi[NPO + tid];
            float a0 = tanhf(xwA + sum.x + biasj);
            float a1 = tanhf(xwB + sum.y + biasj);
            float h0n = decay * hold.x + DT_C * a0;
            float h1n = decay * hold.y + DT_C * a1;
            size_t off = (size_t)t * H_SZ;
            __stcg(states + sidx0 + off, h0n);
            __stcg(states + sidx0 + (size_t)T_SZ * H_SZ + off, h1n);
            float2 hn = make_float2(h0n, h1n);
            __stcg((float2*)(g_hT[cur ^ 1] + (size_t)jg * B_SZ + bg0 + 2 * bp), hn);
            if (t == T_SZ - 1) {
                __stcg(hfinal + (size_t)(bg0 + 2 * bp) * H_SZ + jg, h0n);
                __stcg(hfinal + (size_t)(bg0 + 2 * bp + 1) * H_SZ + jg, h1n);
            } else {
                xwA = __ldcg(states + sidx0 + off + H_SZ);   // prefetch t+1
                xwB = __ldcg(states + sidx0 + (size_t)T_SZ * H_SZ + off + H_SZ);
            }
        }
        cur ^= 1;

        // ---- per-half two-hop barrier (R8-proven idiom, 64-block group) ----
        __syncthreads();
        if (tid == 0) {
            __threadfence();
            g_arrive[blk * FPAD] = t + 1;
        }
        if (leader) {
            if (tid < 64) {
                while (g_arrive[(gbase + tid) * FPAD] < t + 1) { }
            }
            __syncthreads();
            if (tid == 0) {
                __threadfence();
                g_release[bh * FPAD] = t + 1;
            }
        }
        if (tid == 0) {
            while (g_release[bh * FPAD] < t + 1) { }
            __threadfence();
        }
        __syncthreads();
    }
}

// ------------------------------------------------------------------
// Launcher
// ------------------------------------------------------------------
extern "C" void kernel_launch(void* const* d_in, const int* in_sizes, int n_in,
                              void* d_out, int out_size) {
    const float* x   = (const float*)d_in[0];   // [B, T, I]
    const float* W   = (const float*)d_in[1];   // [H, I]
    const float* U   = (const float*)d_in[2];   // [H, H]
    const float* b   = (const float*)d_in[3];   // [H]
    const float* tau = (const float*)d_in[4];   // [H]

    float* hfinal = (float*)d_out;              // [B, H]
    float* states = hfinal + B_SZ * H_SZ;       // [B, T, H]

    cudaFuncSetAttribute(recur_kernel,
                         cudaFuncAttributeMaxDynamicSharedMemorySize,
                         RECUR_SMEM);

    reset_kernel<<<32, 1024>>>();

    dim3 ggrid(H_SZ / GBN, (B_SZ * T_SZ) / GBM);
    gemm_xw<<<ggrid, 256>>>(x, W, states);

    recur_kernel<<<RBLK, 512, RECUR_SMEM>>>(states, hfinal, U, b, tau);
}

// round 10
// speedup vs baseline: 1.1512x; 1.1512x over previous
#include <cuda_runtime.h>
#include <math.h>

#define B_SZ 32
#define T_SZ 1024
#define I_SZ 512
#define H_SZ 1024
#define DT_C 0.1f

typedef unsigned long long ull;

// ---------------- f32x2 packed-math helpers (Blackwell FFMA2) -------------
__device__ __forceinline__ ull ffma2(ull a, ull b, ull c) {
    ull d; asm("fma.rn.f32x2 %0, %1, %2, %3;" : "=l"(d) : "l"(a), "l"(b), "l"(c)); return d;
}
__device__ __forceinline__ ull fadd2(ull a, ull b) {
    ull d; asm("add.rn.f32x2 %0, %1, %2;" : "=l"(d) : "l"(a), "l"(b)); return d;
}
__device__ __forceinline__ ull pack2(float lo, float hi) {
    ull d; asm("mov.b64 %0, {%1, %2};" : "=l"(d) : "f"(lo), "f"(hi)); return d;
}
__device__ __forceinline__ float2 unpack2(ull v) {
    float2 r; asm("mov.b64 {%0, %1}, %2;" : "=f"(r.x), "=f"(r.y) : "l"(v)); return r;
}

// ------------------------------------------------------------------
// Persistent-kernel global state
// g_hT: transposed hidden state double buffer: [2][H][B]  (k-major)
// Barrier flags: one per 128B line; two independent 64-block groups.
// ------------------------------------------------------------------
#define RBLK 128
#define FPAD 32                      // ints per flag slot (128B line)
__device__ float g_hT[2][H_SZ * B_SZ];
__device__ volatile int g_arrive[RBLK * FPAD];
__device__ volatile int g_release[2 * FPAD];

__global__ void reset_kernel() {
    int idx = blockIdx.x * blockDim.x + threadIdx.x;
    if (idx < H_SZ * B_SZ) g_hT[0][idx] = 0.0f;
    if (idx < RBLK * FPAD) g_arrive[idx] = 0;
    if (idx < 2 * FPAD) g_release[idx] = 0;
}

// ------------------------------------------------------------------
// xW GEMM: C[M=B*T, H] = X[M, I] @ W[H, I]^T   (fp32, FFMA2 inner)
// 128x128 block tile, BK=16, 256 threads, 8m x 8n per thread.
// Per kk: 4 LDS.128 (64B) feed 32 FFMA2 -> compute-bound (was LDS-bound).
// ------------------------------------------------------------------
#define GBM 128
#define GBN 128
#define GBK 16
#define WSTR (GBN + 4)

union F4U { float4 f4; ull u[2]; };

__global__ void __launch_bounds__(256, 2) gemm_xw(
    const float* __restrict__ X, const float* __restrict__ W,
    float* __restrict__ C)
{
    __shared__ float Xs[GBK][GBM];
    __shared__ float Ws[GBK][WSTR];
    const int tid = threadIdx.x;
    const int tx = tid & 15;   // 16 -> N (8 cols each)
    const int ty = tid >> 4;   // 16 -> M (8 rows each)
    const int m0 = blockIdx.y * GBM;
    const int n0 = blockIdx.x * GBN;

    ull acc2[4][8];   // [m-pair p][n j]
#pragma unroll
    for (int p = 0; p < 4; p++)
#pragma unroll
        for (int j = 0; j < 8; j++) acc2[p][j] = 0ull;

    for (int k0 = 0; k0 < I_SZ; k0 += GBK) {
        // X tile: 128 rows x 16 k -> Xs[k][m]
#pragma unroll
        for (int pp = 0; pp < 2; pp++) {
            int q = tid + pp * 256;
            int row = q >> 2, qc = q & 3;
            float4 v = *(const float4*)(X + (size_t)(m0 + row) * I_SZ + k0 + qc * 4);
            Xs[qc * 4 + 0][row] = v.x; Xs[qc * 4 + 1][row] = v.y;
            Xs[qc * 4 + 2][row] = v.z; Xs[qc * 4 + 3][row] = v.w;
        }
        // W tile: 128 n-rows x 16 k -> Ws[k][n]
#pragma unroll
        for (int pp = 0; pp < 2; pp++) {
            int q = tid + pp * 256;
            int row = q >> 2, qc = q & 3;
            float4 v = *(const float4*)(W + (size_t)(n0 + row) * I_SZ + k0 + qc * 4);
            Ws[qc * 4 + 0][row] = v.x; Ws[qc * 4 + 1][row] = v.y;
            Ws[qc * 4 + 2][row] = v.z; Ws[qc * 4 + 3][row] = v.w;
        }
        __syncthreads();
#pragma unroll
        for (int kk = 0; kk < GBK; kk++) {
            F4U a0, a1, b0, b1;
            a0.f4 = *(const float4*)&Xs[kk][ty * 8];
            a1.f4 = *(const float4*)&Xs[kk][ty * 8 + 4];
            b0.f4 = *(const float4*)&Ws[kk][tx * 8];
            b1.f4 = *(const float4*)&Ws[kk][tx * 8 + 4];
            ull bd[8];
            bd[0] = pack2(b0.f4.x, b0.f4.x); bd[1] = pack2(b0.f4.y, b0.f4.y);
            bd[2] = pack2(b0.f4.z, b0.f4.z); bd[3] = pack2(b0.f4.w, b0.f4.w);
            bd[4] = pack2(b1.f4.x, b1.f4.x); bd[5] = pack2(b1.f4.y, b1.f4.y);
            bd[6] = pack2(b1.f4.z, b1.f4.z); bd[7] = pack2(b1.f4.w, b1.f4.w);
            ull a2[4] = {a0.u[0], a0.u[1], a1.u[0], a1.u[1]};
#pragma unroll
            for (int p = 0; p < 4; p++)
#pragma unroll
                for (int j = 0; j < 8; j++)
                    acc2[p][j] = ffma2(a2[p], bd[j], acc2[p][j]);
        }
        __syncthreads();
    }
#pragma unroll
    for (int p = 0; p < 4; p++) {
        float2 c[8];
#pragma unroll
        for (int j = 0; j < 8; j++) c[j] = unpack2(acc2[p][j]);
        float4 lo0 = make_float4(c[0].x, c[1].x, c[2].x, c[3].x);
        float4 lo1 = make_float4(c[4].x, c[5].x, c[6].x, c[7].x);
        float4 hi0 = make_float4(c[0].y, c[1].y, c[2].y, c[3].y);
        float4 hi1 = make_float4(c[4].y, c[5].y, c[6].y, c[7].y);
        float* r0 = C + (size_t)(m0 + ty * 8 + 2 * p)     * H_SZ + n0 + tx * 8;
        float* r1 = C + (size_t)(m0 + ty * 8 + 2 * p + 1) * H_SZ + n0 + tx * 8;
        *(float4*)(r0)     = lo0;
        *(float4*)(r0 + 4) = lo1;
        *(float4*)(r1)     = hi0;
        *(float4*)(r1 + 4) = hi1;
    }
}

// ------------------------------------------------------------------
// Persistent recurrence kernel (byte-identical to R8: best known).
// grid = 128 blocks (64 j-tiles x 2 b-halves), 512 threads.
// U in SMEM stride 1025; h staged k-major hs[k][16b] stride 20.
// Barrier: two independent 64-block two-hop groups, line-padded flags.
// ------------------------------------------------------------------
#define JT 16
#define BHALF 16
#define USTR 1025
#define HSTR 20
#define NPO 128
#define RECUR_SMEM ((JT * USTR + H_SZ * HSTR) * 4 + NPO * 64 * 8)

__global__ void __launch_bounds__(512, 1) recur_kernel(
    float* __restrict__ states,      // [B, T, H] (holds xW on entry, states on exit)
    float* __restrict__ hfinal,      // [B, H]
    const float* __restrict__ U,     // [H, H]
    const float* __restrict__ bias,  // [H]
    const float* __restrict__ tau)   // [H]
{
    extern __shared__ float sm[];
    float* Us = sm;                                 // [JT][USTR]
    float* hs = Us + JT * USTR;                     // [1024][HSTR]
    ull* red = (ull*)(hs + H_SZ * HSTR);            // [NPO][64]

    const int tid = threadIdx.x;
    const int blk = blockIdx.x;
    const int jt = blk & 63;
    const int bh = blk >> 6;
    const int j0 = jt * JT;
    const int bg0 = bh * BHALF;
    const int gbase = bh << 6;        // first block of this barrier group
    const bool leader = (jt == 0);    // block 0 / block 64 lead their groups

    const int tb = tid & 1;
    const int tj = (tid >> 1) & 3;
    const int ks = tid >> 3;      // 0..63

    // ---- load U slab into smem: Us[row][k], row = 0..15 ----
    for (int q = tid; q < JT * (H_SZ / 4); q += 512) {
        int row = q >> 8;
        int c = (q & 255) * 4;
        float4 v = *(const float4*)(U + (size_t)(j0 + row) * H_SZ + c);
        float* d = Us + row * USTR + c;
        d[0] = v.x; d[1] = v.y; d[2] = v.z; d[3] = v.w;
    }

    // ---- epilogue (reader) setup: tid < 128, sr = tid & 15 ----
    int po = 0, sr = 0, jg = 0, bp = 0;
    float decay = 0.0f, biasj = 0.0f;
    size_t sidx0 = 0, sidx1 = 0;
    float xwA = 0.0f, xwB = 0.0f;
    if (tid < NPO) {
        int r = tid;
        po = ((r >> 1) & 1) | ((r & 1) << 1) | (((r >> 4) & 1) << 2)
           | (((r >> 5) & 1) << 3) | (((r >> 6) & 1) << 4)
           | (((r >> 2) & 1) << 5) | (((r >> 3) & 1) << 6);
        sr = r & 15;
        int j_loc = po >> 3;
        bp = po & 7;
        jg = j0 + j_loc;
        float it = 1.0f / tau[jg];
        decay = 1.0f - DT_C * it;
        biasj = bias[jg];
        int b_glob = bg0 + 2 * bp;
        sidx0 = (size_t)b_glob * T_SZ * H_SZ + jg;
        sidx1 = sidx0 + (size_t)T_SZ * H_SZ;
        xwA = __ldcg(states + sidx0);   // prefetch t = 0
        xwB = __ldcg(states + sidx1);
    }

    int cur = 0;
    __syncthreads();

    for (int t = 0; t < T_SZ; t++) {
        // ---- stage h^T half-slab: hs[k][0..15] <- g_hT[cur][k][bg0..+15] ----
        const float* gh = g_hT[cur] + bg0;
#pragma unroll
        for (int it8 = 0; it8 < 8; it8++) {
            int q = tid + it8 * 512;
            int k = q >> 2, part = (q & 3) * 4;
            float4 v = __ldcg((const float4*)(gh + (size_t)k * B_SZ + part));
            float* d = hs + k * HSTR + part;
            d[0] = v.x; d[1] = v.y; d[2] = v.z; d[3] = v.w;
        }
        __syncthreads();

        // ---- compute: acc2[jj][m] over k = ks + 64*kq ----
        ull acc2[4][4];
#pragma unroll
        for (int jj = 0; jj < 4; jj++)
#pragma unroll
            for (int m = 0; m < 4; m++) acc2[jj][m] = 0ull;

        const float* urow = Us + tj * 4 * USTR + ks;
#pragma unroll
        for (int kq = 0; kq < 16; kq++) {
            int k = ks + 64 * kq;
            const float* hrow = hs + k * HSTR + 2 * tb;
            ull h0 = *(const ull*)(hrow + 0);
            ull h1 = *(const ull*)(hrow + 4);
            ull h2 = *(const ull*)(hrow + 8);
            ull h3 = *(const ull*)(hrow + 12);
#pragma unroll
            for (int jj = 0; jj < 4; jj++) {
                float us = urow[jj * USTR + 64 * kq];
                ull ud = pack2(us, us);
                acc2[jj][0] = ffma2(ud, h0, acc2[jj][0]);
                acc2[jj][1] = ffma2(ud, h1, acc2[jj][1]);
                acc2[jj][2] = ffma2(ud, h2, acc2[jj][2]);
                acc2[jj][3] = ffma2(ud, h3, acc2[jj][3]);
            }
        }

        // ---- write partials, XOR-swizzled (2-phase-optimal STS.64) ----
#pragma unroll
        for (int jj = 0; jj < 4; jj++)
#pragma unroll
            for (int m = 0; m < 4; m++) {
                int p = (tj * 4 + jj) * 8 + 2 * m + tb;
                int col = ks ^ ((m & 1) | (tb << 1) | (tj << 2));
                red[p * 64 + col] = acc2[jj][m];
            }
        __syncthreads();

        // ---- reduce + pointwise epilogue (128 readers) ----
        if (tid < NPO) {
            ull s01 = 0ull, s23 = 0ull;
#pragma unroll
            for (int i = 0; i < 64; i += 2) {
                s01 = fadd2(s01, red[po * 64 + (i ^ sr)]);
                s23 = fadd2(s23, red[po * 64 + ((i + 1) ^ sr)]);
            }
            float2 sum = unpack2(fadd2(s01, s23));
            float2 hold = *(const float2*)(hs + jg * HSTR + 2 * bp);
            float a0 = tanhf(xwA + sum.x + biasj);
            float a1 = tanhf(xwB + sum.y + biasj);
            float h0n = decay * hold.x + DT_C * a0;
            float h1n = decay * hold.y + DT_C * a1;
            size_t off = (size_t)t * H_SZ;
            __stcg(states + sidx0 + off, h0n);
            __stcg(states + sidx1 + off, h1n);
            float2 hn = make_float2(h0n, h1n);
            __stcg((float2*)(g_hT[cur ^ 1] + (size_t)jg * B_SZ + bg0 + 2 * bp), hn);
            if (t == T_SZ - 1) {
                __stcg(hfinal + (size_t)(bg0 + 2 * bp) * H_SZ + jg, h0n);
                __stcg(hfinal + (size_t)(bg0 + 2 * bp + 1) * H_SZ + jg, h1n);
            } else {
                xwA = __ldcg(states + sidx0 + off + H_SZ);   // prefetch t+1
                xwB = __ldcg(states + sidx1 + off + H_SZ);
            }
        }
        cur ^= 1;

        // ---- per-half two-hop barrier (R8-proven idiom, 64-block group) ----
        __syncthreads();
        if (tid == 0) {
            __threadfence();
            g_arrive[blk * FPAD] = t + 1;
        }
        if (leader) {
            if (tid < 64) {
                while (g_arrive[(gbase + tid) * FPAD] < t + 1) { }
            }
            __syncthreads();
            if (tid == 0) {
                __threadfence();
                g_release[bh * FPAD] = t + 1;
            }
        }
        if (tid == 0) {
            while (g_release[bh * FPAD] < t + 1) { }
            __threadfence();
        }
        __syncthreads();
    }
}

// ------------------------------------------------------------------
// Launcher
// ------------------------------------------------------------------
extern "C" void kernel_launch(void* const* d_in, const int* in_sizes, int n_in,
                              void* d_out, int out_size) {
    const float* x   = (const float*)d_in[0];   // [B, T, I]
    const float* W   = (const float*)d_in[1];   // [H, I]
    const float* U   = (const float*)d_in[2];   // [H, H]
    const float* b   = (const float*)d_in[3];   // [H]
    const float* tau = (const float*)d_in[4];   // [H]

    float* hfinal = (float*)d_out;              // [B, H]
    float* states = hfinal + B_SZ * H_SZ;       // [B, T, H]

    cudaFuncSetAttribute(recur_kernel,
                         cudaFuncAttributeMaxDynamicSharedMemorySize,
                         RECUR_SMEM);

    reset_kernel<<<32, 1024>>>();

    dim3 ggrid(H_SZ / GBN, (B_SZ * T_SZ) / GBM);
    gemm_xw<<<ggrid, 256>>>(x, W, states);

    recur_kernel<<<RBLK, 512, RECUR_SMEM>>>(states, hfinal, U, b, tau);
}

// round 11
// speedup vs baseline: 1.4353x; 1.2468x over previous
#include <cuda_runtime.h>
#include <math.h>

#define B_SZ 32
#define T_SZ 1024
#define I_SZ 512
#define H_SZ 1024
#define DT_C 0.1f

typedef unsigned long long ull;

// ---------------- f32x2 packed-math helpers (Blackwell FFMA2) -------------
__device__ __forceinline__ ull ffma2(ull a, ull b, ull c) {
    ull d; asm("fma.rn.f32x2 %0, %1, %2, %3;" : "=l"(d) : "l"(a), "l"(b), "l"(c)); return d;
}
__device__ __forceinline__ ull fadd2(ull a, ull b) {
    ull d; asm("add.rn.f32x2 %0, %1, %2;" : "=l"(d) : "l"(a), "l"(b)); return d;
}
__device__ __forceinline__ ull pack2(float lo, float hi) {
    ull d; asm("mov.b64 %0, {%1, %2};" : "=l"(d) : "f"(lo), "f"(hi)); return d;
}
__device__ __forceinline__ float2 unpack2(ull v) {
    float2 r; asm("mov.b64 {%0, %1}, %2;" : "=f"(r.x), "=f"(r.y) : "l"(v)); return r;
}
// Acquire load for producer-flag polls (orders subsequent loads after flag).
__device__ __forceinline__ int ld_acq(const volatile int* p) {
    int v;
    asm volatile("ld.acquire.gpu.global.s32 %0, [%1];"
                 : "=r"(v) : "l"((const int*)p) : "memory");
    return v;
}

// ------------------------------------------------------------------
// Persistent-kernel global state
// g_hT: transposed hidden state double buffer: [2][H][B]  (k-major)
// g_arrive[blk]: h for step t+1 published (set end of step t)
// g_staged[blk]: staging of step t complete (set early in step t)
// All flags line-padded, monotonic, single-writer.
// ------------------------------------------------------------------
#define RBLK 128
#define FPAD 32                      // ints per flag slot (128B line)
__device__ float g_hT[2][H_SZ * B_SZ];
__device__ volatile int g_arrive[RBLK * FPAD];
__device__ volatile int g_staged[RBLK * FPAD];

__global__ void reset_kernel() {
    int idx = blockIdx.x * blockDim.x + threadIdx.x;
    if (idx < H_SZ * B_SZ) g_hT[0][idx] = 0.0f;
    if (idx < RBLK * FPAD) { g_arrive[idx] = 0; g_staged[idx] = 0; }
}

// ------------------------------------------------------------------
// xW GEMM: C[M=B*T, H] = X[M, I] @ W[H, I]^T   (fp32, FFMA2 inner)
// 128x64 block tile, BK=16, 256 threads  (R8-proven)
// ------------------------------------------------------------------
#define GBM 128
#define GBN 64
#define GBK 16

union F4U { float4 f4; ull u[2]; };

__global__ void __launch_bounds__(256) gemm_xw(
    const float* __restrict__ X, const float* __restrict__ W,
    float* __restrict__ C)
{
    __shared__ float Xs[GBK][GBM];
    __shared__ float Ws[GBK][GBN + 4];
    const int tid = threadIdx.x;
    const int tx = tid & 15;   // 16 -> N
    const int ty = tid >> 4;   // 16 -> M
    const int m0 = blockIdx.y * GBM;
    const int n0 = blockIdx.x * GBN;

    ull acc2[4][4];   // [m-pair p][n j]
#pragma unroll
    for (int p = 0; p < 4; p++)
#pragma unroll
        for (int j = 0; j < 4; j++) acc2[p][j] = 0ull;

    for (int k0 = 0; k0 < I_SZ; k0 += GBK) {
#pragma unroll
        for (int pp = 0; pp < 2; pp++) {
            int q = tid + pp * 256;
            int row = q >> 2, qc = q & 3;
            float4 v = *(const float4*)(X + (size_t)(m0 + row) * I_SZ + k0 + qc * 4);
            Xs[qc * 4 + 0][row] = v.x; Xs[qc * 4 + 1][row] = v.y;
            Xs[qc * 4 + 2][row] = v.z; Xs[qc * 4 + 3][row] = v.w;
        }
        {
            int row = tid >> 2, qc = tid & 3;
            float4 v = *(const float4*)(W + (size_t)(n0 + row) * I_SZ + k0 + qc * 4);
            Ws[qc * 4 + 0][row] = v.x; Ws[qc * 4 + 1][row] = v.y;
            Ws[qc * 4 + 2][row] = v.z; Ws[qc * 4 + 3][row] = v.w;
        }
        __syncthreads();
#pragma unroll
        for (int kk = 0; kk < GBK; kk++) {
            F4U a0, a1;
            a0.f4 = *(const float4*)&Xs[kk][ty * 8];
            a1.f4 = *(const float4*)&Xs[kk][ty * 8 + 4];
            float4 bv = *(const float4*)&Ws[kk][tx * 4];
            ull bd[4];
            bd[0] = pack2(bv.x, bv.x); bd[1] = pack2(bv.y, bv.y);
            bd[2] = pack2(bv.z, bv.z); bd[3] = pack2(bv.w, bv.w);
            ull a2[4] = {a0.u[0], a0.u[1], a1.u[0], a1.u[1]};
#pragma unroll
            for (int p = 0; p < 4; p++)
#pragma unroll
                for (int j = 0; j < 4; j++)
                    acc2[p][j] = ffma2(a2[p], bd[j], acc2[p][j]);
        }
        __syncthreads();
    }
#pragma unroll
    for (int p = 0; p < 4; p++) {
        float2 c0 = unpack2(acc2[p][0]);
        float2 c1 = unpack2(acc2[p][1]);
        float2 c2 = unpack2(acc2[p][2]);
        float2 c3 = unpack2(acc2[p][3]);
        float4 lo = make_float4(c0.x, c1.x, c2.x, c3.x);
        float4 hi = make_float4(c0.y, c1.y, c2.y, c3.y);
        *(float4*)(C + (size_t)(m0 + ty * 8 + 2 * p)     * H_SZ + n0 + tx * 4) = lo;
        *(float4*)(C + (size_t)(m0 + ty * 8 + 2 * p + 1) * H_SZ + n0 + tx * 4) = hi;
    }
}

// ------------------------------------------------------------------
// Persistent recurrence kernel (R8 compute path; dataflow sync).
// grid = 128 blocks (64 j-tiles x 2 b-halves), 512 threads.
// Staging: 64 chunks of 1KB, each gated on its producer's flag.
// Write permission: all same-bh blocks staged step t-1 (poll under reduce).
// ------------------------------------------------------------------
#define JT 16
#define BHALF 16
#define USTR 1025
#define HSTR 20
#define NPO 128
#define RECUR_SMEM ((JT * USTR + H_SZ * HSTR) * 4 + NPO * 64 * 8)

__global__ void __launch_bounds__(512, 1) recur_kernel(
    float* __restrict__ states,      // [B, T, H] (holds xW on entry, states on exit)
    float* __restrict__ hfinal,      // [B, H]
    const float* __restrict__ U,     // [H, H]
    const float* __restrict__ bias,  // [H]
    const float* __restrict__ tau)   // [H]
{
    extern __shared__ float sm[];
    float* Us = sm;                                 // [JT][USTR]
    float* hs = Us + JT * USTR;                     // [1024][HSTR]
    ull* red = (ull*)(hs + H_SZ * HSTR);            // [NPO][64]

    const int tid = threadIdx.x;
    const int blk = blockIdx.x;
    const int jt = blk & 63;
    const int bh = blk >> 6;
    const int j0 = jt * JT;
    const int bg0 = bh * BHALF;
    const int gbase = bh << 6;        // first block of this flag group

    const int tb = tid & 1;
    const int tj = (tid >> 1) & 3;
    const int ks = tid >> 3;      // 0..63

    // ---- staging assignment: 64 chunks x 8 threads ----
    const int ch = ((tid >> 3) + jt + 1) & 63;   // chunk (16 k-rows), offset start
    const int lc = tid & 7;                       // lane within chunk
    const volatile int* pflag = &g_arrive[(gbase | ch) * FPAD];

    // ---- load U slab into smem: Us[row][k], row = 0..15 ----
    for (int q = tid; q < JT * (H_SZ / 4); q += 512) {
        int row = q >> 8;
        int c = (q & 255) * 4;
        float4 v = *(const float4*)(U + (size_t)(j0 + row) * H_SZ + c);
        float* d = Us + row * USTR + c;
        d[0] = v.x; d[1] = v.y; d[2] = v.z; d[3] = v.w;
    }

    // ---- epilogue (reader) setup: tid < 128, sr = tid & 15 ----
    int po = 0, sr = 0, jg = 0, bp = 0;
    float decay = 0.0f, biasj = 0.0f;
    size_t sidx0 = 0, sidx1 = 0;
    float xwA = 0.0f, xwB = 0.0f;
    if (tid < NPO) {
        int r = tid;
        po = ((r >> 1) & 1) | ((r & 1) << 1) | (((r >> 4) & 1) << 2)
           | (((r >> 5) & 1) << 3) | (((r >> 6) & 1) << 4)
           | (((r >> 2) & 1) << 5) | (((r >> 3) & 1) << 6);
        sr = r & 15;
        int j_loc = po >> 3;
        bp = po & 7;
        jg = j0 + j_loc;
        float it = 1.0f / tau[jg];
        decay = 1.0f - DT_C * it;
        biasj = bias[jg];
        int b_glob = bg0 + 2 * bp;
        sidx0 = (size_t)b_glob * T_SZ * H_SZ + jg;
        sidx1 = sidx0 + (size_t)T_SZ * H_SZ;
        xwA = __ldcg(states + sidx0);   // prefetch t = 0
        xwB = __ldcg(states + sidx1);
    }

    int cur = 0;
    __syncthreads();

    for (int t = 0; t < T_SZ; t++) {
        // ---- pipelined staging: copy each chunk as its producer is ready --
        {
            const float* gsrc = g_hT[cur] + bg0 + (size_t)(16 * ch) * B_SZ;
            float* hdst = hs + (16 * ch) * HSTR;
            while (ld_acq(pflag) < t) { }
#pragma unroll
            for (int i = 0; i < 8; i++) {
                int f = lc + 8 * i;                 // 0..63
                int row = f >> 2, part = (f & 3) * 4;
                float4 v = __ldcg((const float4*)(gsrc + (size_t)row * B_SZ + part));
                float* d = hdst + row * HSTR + part;
                d[0] = v.x; d[1] = v.y; d[2] = v.z; d[3] = v.w;
            }
        }
        __syncthreads();
        if (tid == 0) {
            __threadfence();
            g_staged[blk * FPAD] = t + 1;   // "done reading g_hT[cur]"
        }

        // ---- compute: acc2[jj][m] over k = ks + 64*kq ----
        ull acc2[4][4];
#pragma unroll
        for (int jj = 0; jj < 4; jj++)
#pragma unroll
            for (int m = 0; m < 4; m++) acc2[jj][m] = 0ull;

        const float* urow = Us + tj * 4 * USTR + ks;
#pragma unroll
        for (int kq = 0; kq < 16; kq++) {
            int k = ks + 64 * kq;
            const float* hrow = hs + k * HSTR + 2 * tb;
            ull h0 = *(const ull*)(hrow + 0);
            ull h1 = *(const ull*)(hrow + 4);
            ull h2 = *(const ull*)(hrow + 8);
            ull h3 = *(const ull*)(hrow + 12);
#pragma unroll
            for (int jj = 0; jj < 4; jj++) {
                float us = urow[jj * USTR + 64 * kq];
                ull ud = pack2(us, us);
                acc2[jj][0] = ffma2(ud, h0, acc2[jj][0]);
                acc2[jj][1] = ffma2(ud, h1, acc2[jj][1]);
                acc2[jj][2] = ffma2(ud, h2, acc2[jj][2]);
                acc2[jj][3] = ffma2(ud, h3, acc2[jj][3]);
            }
        }

        // ---- write partials, XOR-swizzled (2-phase-optimal STS.64) ----
#pragma unroll
        for (int jj = 0; jj < 4; jj++)
#pragma unroll
            for (int m = 0; m < 4; m++) {
                int p = (tj * 4 + jj) * 8 + 2 * m + tb;
                int col = ks ^ ((m & 1) | (tb << 1) | (tj << 2));
                red[p * 64 + col] = acc2[jj][m];
            }
        __syncthreads();

        // ---- reduce (tid<128)  ||  write-permission poll (tid 256..319) ---
        float2 sum = make_float2(0.0f, 0.0f);
        float2 hold = make_float2(0.0f, 0.0f);
        if (tid < NPO) {
            ull s01 = 0ull, s23 = 0ull;
#pragma unroll
            for (int i = 0; i < 64; i += 2) {
                s01 = fadd2(s01, red[po * 64 + (i ^ sr)]);
                s23 = fadd2(s23, red[po * 64 + ((i + 1) ^ sr)]);
            }
            sum = unpack2(fadd2(s01, s23));
            hold = *(const float2*)(hs + jg * HSTR + 2 * bp);
        } else if (tid >= 256 && tid < 320) {
            // all same-bh blocks must have staged step t-1 before we
            // overwrite g_hT[cur^1] (the buffer they read at step t-1)
            while (g_staged[(gbase + (tid - 256)) * FPAD] < t) { }
        }
        __syncthreads();

        // ---- pointwise epilogue + h publish (128 writers) ----
        if (tid < NPO) {
            float a0 = tanhf(xwA + sum.x + biasj);
            float a1 = tanhf(xwB + sum.y + biasj);
            float h0n = decay * hold.x + DT_C * a0;
            float h1n = decay * hold.y + DT_C * a1;
            size_t off = (size_t)t * H_SZ;
            __stcg(states + sidx0 + off, h0n);
            __stcg(states + sidx1 + off, h1n);
            float2 hn = make_float2(h0n, h1n);
            __stcg((float2*)(g_hT[cur ^ 1] + (size_t)jg * B_SZ + bg0 + 2 * bp), hn);
            if (t == T_SZ - 1) {
                __stcg(hfinal + (size_t)(bg0 + 2 * bp) * H_SZ + jg, h0n);
                __stcg(hfinal + (size_t)(bg0 + 2 * bp + 1) * H_SZ + jg, h1n);
            } else {
                xwA = __ldcg(states + sidx0 + off + H_SZ);   // prefetch t+1
                xwB = __ldcg(states + sidx1 + off + H_SZ);
            }
        }
        cur ^= 1;

        // ---- publish: h_{t+1} ready (R8-proven fence+flag idiom) ----------
        __syncthreads();
        if (tid == 0) {
            __threadfence();
            g_arrive[blk * FPAD] = t + 1;
        }
    }
}

// ------------------------------------------------------------------
// Launcher
// ------------------------------------------------------------------
extern "C" void kernel_launch(void* const* d_in, const int* in_sizes, int n_in,
                              void* d_out, int out_size) {
    const float* x   = (const float*)d_in[0];   // [B, T, I]
    const float* W   = (const float*)d_in[1];   // [H, I]
    const float* U   = (const float*)d_in[2];   // [H, H]
    const float* b   = (const float*)d_in[3];   // [H]
    const float* tau = (const float*)d_in[4];   // [H]

    float* hfinal = (float*)d_out;              // [B, H]
    float* states = hfinal + B_SZ * H_SZ;       // [B, T, H]

    cudaFuncSetAttribute(recur_kernel,
                         cudaFuncAttributeMaxDynamicSharedMemorySize,
                         RECUR_SMEM);

    reset_kernel<<<32, 1024>>>();

    dim3 ggrid(H_SZ / GBN, (B_SZ * T_SZ) / GBM);
    gemm_xw<<<ggrid, 256>>>(x, W, states);

    recur_kernel<<<RBLK, 512, RECUR_SMEM>>>(states, hfinal, U, b, tau);
}